// round 3
// baseline (speedup 1.0000x reference)
#include <cuda_runtime.h>
#include <cstdint>

// Gent hyperelastic energy over N 3x3 deformation gradients (elementwise).
//   I1 = ||F||_F^2 ; J = det(F) ; I1bar = I1 * J^(-2/3)
//   vol = (J^2-1)/2 - ln J ;  w = A*ln(1 - (I1bar-3)/JM) + B*vol^4
//   A = -(G/2)*JM = -1442307.6923..., B = K/2 = 31250, JM = 100.
//
// Persistent-CTA, double-buffered cp.async pipeline:
//   tile = 512 matrices = 4608 floats = 18 KB; 2 buffers = 36 KB smem.
//   While computing buffer k, loads for tile k+1 are in flight.
// Math: single MUFU.LG2 gives both ln(J) and J^(-2/3) (via EX2);
//   ln(1-u) evaluated by 5-term series (u <= ~0.03, err < 1e-8 abs).

#define THREADS 256
#define TILE_MATS 512
#define TILE_F (TILE_MATS * 9)        // 4608 floats
#define TILE_V4 (TILE_F / 4)          // 1152 float4
#define NCTA 888                      // ~6 per SM on 148 SMs

__device__ __forceinline__ void cp_async16(void* smem_dst, const void* gmem_src) {
    uint32_t s = (uint32_t)__cvta_generic_to_shared(smem_dst);
    asm volatile("cp.async.cg.shared.global [%0], [%1], 16;\n"
                 :: "r"(s), "l"(gmem_src));
}

__global__ __launch_bounds__(THREADS)
void gent_kernel(const float* __restrict__ x, float* __restrict__ w, int n)
{
    __shared__ float sx[2][TILE_F];   // 36 KB

    const int tid = threadIdx.x;
    const int num_tiles = (n + TILE_MATS - 1) / TILE_MATS;     // 7813
    const long long total_f4 = ((long long)n * 9) >> 2;        // 9,000,000

    const float4* gx4 = reinterpret_cast<const float4*>(x);

    int tile = blockIdx.x;
    if (tile >= num_tiles) return;

    // Prologue: issue loads for first tile.
    {
        long long base = (long long)tile * TILE_V4;
        #pragma unroll
        for (int i = tid; i < TILE_V4; i += THREADS) {
            long long g4 = base + i;
            if (g4 < total_f4) cp_async16(&sx[0][i * 4], &gx4[g4]);
        }
        asm volatile("cp.async.commit_group;\n");
    }

    const float A = -1442307.6923076923f;   // -(G/2)*JM
    const float B = 31250.0f;               // K/2
    const float JM_inv = 0.01f;
    const float LN2 = 0.69314718055994531f;

    int buf = 0;
    while (true) {
        const int next = tile + NCTA;
        if (next < num_tiles) {
            // Issue next tile's loads into the other buffer.
            long long base = (long long)next * TILE_V4;
            #pragma unroll
            for (int i = tid; i < TILE_V4; i += THREADS) {
                long long g4 = base + i;
                if (g4 < total_f4) cp_async16(&sx[buf ^ 1][i * 4], &gx4[g4]);
            }
            asm volatile("cp.async.commit_group;\n");
            asm volatile("cp.async.wait_group 1;\n" ::: "memory");
        } else {
            asm volatile("cp.async.wait_group 0;\n" ::: "memory");
        }
        __syncthreads();

        // Compute 2 matrices per thread from the ready buffer.
        const long long mat_base = (long long)tile * TILE_MATS;
        #pragma unroll
        for (int m = 0; m < 2; m++) {
            const int local = tid + m * THREADS;
            const long long gi = mat_base + local;
            if (gi < n) {
                const float* mm = &sx[buf][local * 9];  // stride 9: conflict-free
                float a00 = mm[0], a01 = mm[1], a02 = mm[2];
                float a10 = mm[3], a11 = mm[4], a12 = mm[5];
                float a20 = mm[6], a21 = mm[7], a22 = mm[8];

                float I1 = a00*a00 + a01*a01 + a02*a02
                         + a10*a10 + a11*a11 + a12*a12
                         + a20*a20 + a21*a21 + a22*a22;

                float J = a00*(a11*a22 - a12*a21)
                        - a01*(a10*a22 - a12*a20)
                        + a02*(a10*a21 - a11*a20);

                // One LG2 feeds both ln(J) and J^(-2/3).
                float l2 = __log2f(J);
                float lnJ = l2 * LN2;
                float Jm23 = exp2f(-0.66666666666666667f * l2);

                float I1bar = I1 * Jm23;

                float vol = fmaf(0.5f, J*J, -0.5f) - lnJ;
                float vol2 = vol * vol;
                float vol4 = vol2 * vol2;

                // ln(1-u) = -(u + u^2/2 + u^3/3 + u^4/4 + u^5/5), u small.
                float u = (I1bar - 3.0f) * JM_inv;
                float p = fmaf(u, 0.2f, 0.25f);
                p = fmaf(u, p, 0.33333333333333333f);
                p = fmaf(u, p, 0.5f);
                p = fmaf(u, p, 1.0f);
                float ln1mu = -u * p;

                w[gi] = fmaf(B, vol4, A * ln1mu);
            }
        }
        __syncthreads();   // all reads done before next overwrite of sx[buf]

        if (next >= num_tiles) break;
        tile = next;
        buf ^= 1;
    }
}

extern "C" void kernel_launch(void* const* d_in, const int* in_sizes, int n_in,
                              void* d_out, int out_size)
{
    const float* x = (const float*)d_in[0];
    float* w = (float*)d_out;
    const int n = out_size;   // 4,000,000
    gent_kernel<<<NCTA, THREADS>>>(x, w, n);
}

// round 4
// speedup vs baseline: 1.0377x; 1.0377x over previous
#include <cuda_runtime.h>
#include <cstdint>

// Gent hyperelastic energy over N 3x3 deformation gradients (elementwise).
//   I1 = ||F||_F^2 ; J = det(F) ; I1bar = I1 * J^(-2/3)
//   vol = (J^2-1)/2 - ln J ;  w = A*ln(1 - (I1bar-3)/JM) + B*vol^4
//   A = -(G/2)*JM = -1442307.6923..., B = K/2 = 31250, JM = 100.
//
// One-shot tiles (self-balancing grid), small CTAs for high CTA/SM count:
//   128 threads, 512 matrices/CTA = 18 KB smem -> ~12 CTAs/SM.
//   9 back-to-back cp.async16 per thread (MLP=9), single commit/wait.
// Cheap math: one MUFU.LG2 feeds ln(J) and J^(-2/3); ln(1-u) by 5-term
// series (|u| <= ~0.03, abs err < 1e-8).

#define THREADS 128
#define MPT 4
#define TILE_MATS (THREADS * MPT)          // 512
#define TILE_F (TILE_MATS * 9)             // 4608 floats = 18 KB
#define TILE_V4 (TILE_F / 4)               // 1152 -> 9 per thread

__device__ __forceinline__ void cp_async16(void* smem_dst, const void* gmem_src) {
    uint32_t s = (uint32_t)__cvta_generic_to_shared(smem_dst);
    asm volatile("cp.async.cg.shared.global [%0], [%1], 16;\n"
                 :: "r"(s), "l"(gmem_src));
}

__global__ __launch_bounds__(THREADS)
void gent_kernel(const float* __restrict__ x, float* __restrict__ w, int n)
{
    __shared__ float sx[TILE_F];

    const int tid = threadIdx.x;
    const long long base_f4 = (long long)blockIdx.x * TILE_V4;
    const long long total_f4 = ((long long)n * 9) >> 2;

    const float4* gx4 = reinterpret_cast<const float4*>(x);

    // 9 independent coalesced 16B async copies per thread.
    #pragma unroll
    for (int i = 0; i < 9; i++) {
        const int idx = tid + i * THREADS;
        const long long g4 = base_f4 + idx;
        if (g4 < total_f4) cp_async16(&sx[idx * 4], &gx4[g4]);
    }
    asm volatile("cp.async.commit_group;\n");
    asm volatile("cp.async.wait_group 0;\n" ::: "memory");
    __syncthreads();

    const float A = -1442307.6923076923f;   // -(G/2)*JM
    const float B = 31250.0f;               // K/2
    const float JM_inv = 0.01f;
    const float LN2 = 0.69314718055994531f;

    const long long mat_base = (long long)blockIdx.x * TILE_MATS;

    #pragma unroll
    for (int m = 0; m < MPT; m++) {
        const int local = tid + m * THREADS;     // strided: conflict-free smem
        const long long gi = mat_base + local;
        if (gi < n) {
            const float* mm = &sx[local * 9];
            float a00 = mm[0], a01 = mm[1], a02 = mm[2];
            float a10 = mm[3], a11 = mm[4], a12 = mm[5];
            float a20 = mm[6], a21 = mm[7], a22 = mm[8];

            float I1 = a00*a00 + a01*a01 + a02*a02
                     + a10*a10 + a11*a11 + a12*a12
                     + a20*a20 + a21*a21 + a22*a22;

            float J = a00*(a11*a22 - a12*a21)
                    - a01*(a10*a22 - a12*a20)
                    + a02*(a10*a21 - a11*a20);

            // One LG2 feeds both ln(J) and J^(-2/3).
            float l2 = __log2f(J);
            float lnJ = l2 * LN2;
            float Jm23 = exp2f(-0.66666666666666667f * l2);

            float I1bar = I1 * Jm23;

            float vol = fmaf(0.5f, J*J, -0.5f) - lnJ;
            float vol2 = vol * vol;
            float vol4 = vol2 * vol2;

            // ln(1-u) = -(u + u^2/2 + u^3/3 + u^4/4 + u^5/5)
            float u = (I1bar - 3.0f) * JM_inv;
            float p = fmaf(u, 0.2f, 0.25f);
            p = fmaf(u, p, 0.33333333333333333f);
            p = fmaf(u, p, 0.5f);
            p = fmaf(u, p, 1.0f);
            float ln1mu = -u * p;

            w[gi] = fmaf(B, vol4, A * ln1mu);
        }
    }
}

extern "C" void kernel_launch(void* const* d_in, const int* in_sizes, int n_in,
                              void* d_out, int out_size)
{
    const float* x = (const float*)d_in[0];
    float* w = (float*)d_out;
    const int n = out_size;  // 4,000,000
    const int blocks = (n + TILE_MATS - 1) / TILE_MATS;  // 7813
    gent_kernel<<<blocks, THREADS>>>(x, w, n);
}

// round 5
// speedup vs baseline: 1.1138x; 1.0733x over previous
#include <cuda_runtime.h>
#include <cstdint>

// Gent hyperelastic energy over N 3x3 deformation gradients (elementwise).
//   I1 = ||F||_F^2 ; J = det(F) ; I1bar = I1 * J^(-2/3)
//   vol = (J^2-1)/2 - ln J ;  w = A*ln(1 - (I1bar-3)/JM) + B*vol^4
//   A = -(G/2)*JM = -1442307.6923..., B = K/2 = 31250, JM = 100.
//
// One-shot tiles: 128 threads, 512 matrices/CTA = 18 KB smem (~12 CTAs/SM).
// Tile fetched by a single cp.async.bulk (TMA) + mbarrier per CTA — the whole
// 18 KB is outstanding immediately, zero per-element load instructions.
// Last (partial) tile handled by clamping the bulk byte count.
// Math: one MUFU.LG2 feeds ln(J) and J^(-2/3); ln(1-u) via 5-term series.
// Output written with streaming stores (st.global.cs).

#define THREADS 128
#define MPT 4
#define TILE_MATS (THREADS * MPT)            // 512
#define TILE_F (TILE_MATS * 9)               // 4608 floats
#define TILE_BYTES (TILE_F * 4)              // 18432 bytes

__global__ __launch_bounds__(THREADS)
void gent_kernel(const float* __restrict__ x, float* __restrict__ w, int n)
{
    __shared__ alignas(128) float sx[TILE_F];
    __shared__ alignas(8) uint64_t mbar;

    const int tid = threadIdx.x;
    const size_t total_bytes = (size_t)n * 36u;
    const size_t base_bytes = (size_t)blockIdx.x * TILE_BYTES;

    uint32_t smem_dst = (uint32_t)__cvta_generic_to_shared(sx);
    uint32_t mbar_a = (uint32_t)__cvta_generic_to_shared(&mbar);

    if (tid == 0) {
        asm volatile("mbarrier.init.shared::cta.b64 [%0], 1;" :: "r"(mbar_a) : "memory");
    }
    __syncthreads();

    if (tid == 0) {
        size_t rem = total_bytes - base_bytes;
        uint32_t bytes = rem < (size_t)TILE_BYTES ? (uint32_t)rem : (uint32_t)TILE_BYTES;
        const char* gsrc = reinterpret_cast<const char*>(x) + base_bytes;
        asm volatile("mbarrier.arrive.expect_tx.shared::cta.b64 _, [%0], %1;"
                     :: "r"(mbar_a), "r"(bytes) : "memory");
        asm volatile("cp.async.bulk.shared::cta.global.mbarrier::complete_tx::bytes "
                     "[%0], [%1], %2, [%3];"
                     :: "r"(smem_dst), "l"(gsrc), "r"(bytes), "r"(mbar_a) : "memory");
    }

    // All threads wait for the bulk copy (phase 0).
    asm volatile(
        "{\n\t"
        ".reg .pred P;\n\t"
        "LAB_WAIT_%=:\n\t"
        "mbarrier.try_wait.parity.shared::cta.b64 P, [%0], 0, 0x989680;\n\t"
        "@P bra LAB_DONE_%=;\n\t"
        "bra LAB_WAIT_%=;\n\t"
        "LAB_DONE_%=:\n\t"
        "}"
        :: "r"(mbar_a) : "memory");
    __syncthreads();

    const float A = -1442307.6923076923f;   // -(G/2)*JM
    const float B = 31250.0f;               // K/2
    const float JM_inv = 0.01f;
    const float LN2 = 0.69314718055994531f;

    const long long mat_base = (long long)blockIdx.x * TILE_MATS;

    #pragma unroll
    for (int m = 0; m < MPT; m++) {
        const int local = tid + m * THREADS;     // strided: conflict-free smem
        const long long gi = mat_base + local;
        if (gi < n) {
            const float* mm = &sx[local * 9];
            float a00 = mm[0], a01 = mm[1], a02 = mm[2];
            float a10 = mm[3], a11 = mm[4], a12 = mm[5];
            float a20 = mm[6], a21 = mm[7], a22 = mm[8];

            float I1 = a00*a00 + a01*a01 + a02*a02
                     + a10*a10 + a11*a11 + a12*a12
                     + a20*a20 + a21*a21 + a22*a22;

            float J = a00*(a11*a22 - a12*a21)
                    - a01*(a10*a22 - a12*a20)
                    + a02*(a10*a21 - a11*a20);

            // One LG2 feeds both ln(J) and J^(-2/3).
            float l2 = __log2f(J);
            float lnJ = l2 * LN2;
            float Jm23 = exp2f(-0.66666666666666667f * l2);

            float I1bar = I1 * Jm23;

            float vol = fmaf(0.5f, J*J, -0.5f) - lnJ;
            float vol2 = vol * vol;
            float vol4 = vol2 * vol2;

            // ln(1-u) = -(u + u^2/2 + u^3/3 + u^4/4 + u^5/5)
            float u = (I1bar - 3.0f) * JM_inv;
            float p = fmaf(u, 0.2f, 0.25f);
            p = fmaf(u, p, 0.33333333333333333f);
            p = fmaf(u, p, 0.5f);
            p = fmaf(u, p, 1.0f);
            float ln1mu = -u * p;

            float wv = fmaf(B, vol4, A * ln1mu);
            __stcs(&w[gi], wv);   // streaming store: don't pollute L2
        }
    }
}

extern "C" void kernel_launch(void* const* d_in, const int* in_sizes, int n_in,
                              void* d_out, int out_size)
{
    const float* x = (const float*)d_in[0];
    float* w = (float*)d_out;
    const int n = out_size;  // 4,000,000
    const int blocks = (n + TILE_MATS - 1) / TILE_MATS;  // 7813
    gent_kernel<<<blocks, THREADS>>>(x, w, n);
}

// round 7
// speedup vs baseline: 1.2005x; 1.0778x over previous
#include <cuda_runtime.h>
#include <cstdint>

// Gent hyperelastic energy over N 3x3 deformation gradients (elementwise).
//   I1 = ||F||_F^2 ; J = det(F) ; I1bar = I1 * J^(-2/3)
//   vol = (J^2-1)/2 - ln J ;  w = A*ln(1 - (I1bar-3)/JM) + B*vol^4
//   A = -(G/2)*JM = -1442307.6923..., B = K/2 = 31250, JM = 100.
//
// One-shot small tiles for maximum CTA-level memory concurrency:
//   128 threads, 256 matrices/CTA = 9 KB smem -> ~24 resident CTAs/SM.
//   Whole tile fetched by ONE cp.async.bulk (TMA) + mbarrier; zero
//   per-element load instructions. Partial last tile via clamped byte count.
// Math: one MUFU.LG2 feeds ln(J) and J^(-2/3); ln(1-u) via 5-term series.
// Output: streaming stores (st.global.cs).

#define THREADS 128
#define MPT 2
#define TILE_MATS (THREADS * MPT)            // 256
#define TILE_F (TILE_MATS * 9)               // 2304 floats
#define TILE_BYTES (TILE_F * 4)              // 9216 bytes

__global__ __launch_bounds__(THREADS)
void gent_kernel(const float* __restrict__ x, float* __restrict__ w, int n)
{
    __shared__ alignas(128) float sx[TILE_F];
    __shared__ alignas(8) uint64_t mbar;

    const int tid = threadIdx.x;
    const size_t total_bytes = (size_t)n * 36u;
    const size_t base_bytes = (size_t)blockIdx.x * TILE_BYTES;

    uint32_t smem_dst = (uint32_t)__cvta_generic_to_shared(sx);
    uint32_t mbar_a = (uint32_t)__cvta_generic_to_shared(&mbar);

    if (tid == 0) {
        asm volatile("mbarrier.init.shared::cta.b64 [%0], 1;" :: "r"(mbar_a) : "memory");
    }
    __syncthreads();

    if (tid == 0) {
        size_t rem = total_bytes - base_bytes;
        uint32_t bytes = rem < (size_t)TILE_BYTES ? (uint32_t)rem : (uint32_t)TILE_BYTES;
        const char* gsrc = reinterpret_cast<const char*>(x) + base_bytes;
        asm volatile("mbarrier.arrive.expect_tx.shared::cta.b64 _, [%0], %1;"
                     :: "r"(mbar_a), "r"(bytes) : "memory");
        asm volatile("cp.async.bulk.shared::cta.global.mbarrier::complete_tx::bytes "
                     "[%0], [%1], %2, [%3];"
                     :: "r"(smem_dst), "l"(gsrc), "r"(bytes), "r"(mbar_a) : "memory");
    }

    // All threads wait for the bulk copy (phase 0).
    asm volatile(
        "{\n\t"
        ".reg .pred P;\n\t"
        "LAB_WAIT_%=:\n\t"
        "mbarrier.try_wait.parity.shared::cta.b64 P, [%0], 0, 0x989680;\n\t"
        "@P bra LAB_DONE_%=;\n\t"
        "bra LAB_WAIT_%=;\n\t"
        "LAB_DONE_%=:\n\t"
        "}"
        :: "r"(mbar_a) : "memory");

    const float A = -1442307.6923076923f;   // -(G/2)*JM
    const float B = 31250.0f;               // K/2
    const float JM_inv = 0.01f;
    const float LN2 = 0.69314718055994531f;

    const long long mat_base = (long long)blockIdx.x * TILE_MATS;

    #pragma unroll
    for (int m = 0; m < MPT; m++) {
        const int local = tid + m * THREADS;     // strided: conflict-free smem
        const long long gi = mat_base + local;
        if (gi < n) {
            const float* mm = &sx[local * 9];
            float a00 = mm[0], a01 = mm[1], a02 = mm[2];
            float a10 = mm[3], a11 = mm[4], a12 = mm[5];
            float a20 = mm[6], a21 = mm[7], a22 = mm[8];

            float I1 = a00*a00 + a01*a01 + a02*a02
                     + a10*a10 + a11*a11 + a12*a12
                     + a20*a20 + a21*a21 + a22*a22;

            float J = a00*(a11*a22 - a12*a21)
                    - a01*(a10*a22 - a12*a20)
                    + a02*(a10*a21 - a11*a20);

            // One LG2 feeds both ln(J) and J^(-2/3).
            float l2 = __log2f(J);
            float lnJ = l2 * LN2;
            float Jm23 = exp2f(-0.66666666666666667f * l2);

            float I1bar = I1 * Jm23;

            float vol = fmaf(0.5f, J*J, -0.5f) - lnJ;
            float vol2 = vol * vol;
            float vol4 = vol2 * vol2;

            // ln(1-u) = -(u + u^2/2 + u^3/3 + u^4/4 + u^5/5)
            float u = (I1bar - 3.0f) * JM_inv;
            float p = fmaf(u, 0.2f, 0.25f);
            p = fmaf(u, p, 0.33333333333333333f);
            p = fmaf(u, p, 0.5f);
            p = fmaf(u, p, 1.0f);
            float ln1mu = -u * p;

            float wv = fmaf(B, vol4, A * ln1mu);
            __stcs(&w[gi], wv);   // streaming store: don't pollute L2
        }
    }
}

extern "C" void kernel_launch(void* const* d_in, const int* in_sizes, int n_in,
                              void* d_out, int out_size)
{
    const float* x = (const float*)d_in[0];
    float* w = (float*)d_out;
    const int n = out_size;  // 4,000,000
    const int blocks = (n + TILE_MATS - 1) / TILE_MATS;  // 15625
    gent_kernel<<<blocks, THREADS>>>(x, w, n);
}